// round 17
// baseline (speedup 1.0000x reference)
#include <cuda_runtime.h>
#include <cuda_fp16.h>

// ---------------------------------------------------------------------------
// GCN link prediction, CSR-gather formulation (R14 structure + 3 cuts):
//   layer1: hs1 = dinv*(x@W1) fp16 (k_scale applies dinv after gemm1||build)
//   agg1:   acc = hs1[c] + sum hs1[src]; bufC = fp16(relu(dinv*acc + b1))
//   gemm2:  bufA = fp16(dinv*(bufC @ W2))   [4 nodes/thread]
//   agg2:   acc = bufA[c] + sum bufA[src]; z = fp16(dinv*acc + b2)
//   decode: dot64 over fp16 z.
// ---------------------------------------------------------------------------

#define N_NODES 50000
#define E_TRAIN 1600000
#define EP      200000
#define EN      200000
#define F_IN    50
#define HID     50
#define DOUT    64
#define PAD     64

#define SCAN_B  1024
#define SCAN_NBLK ((N_NODES + SCAN_B - 1) / SCAN_B)   // 49

__device__ __align__(256) __half g_bufA[N_NODES * PAD]; // gather src (hs1, then hs2)
__device__ __align__(256) __half g_bufC[N_NODES * PAD]; // h1 fp16
__device__ __align__(256) __half g_z[N_NODES * PAD];    // final z fp16
__device__ int   g_deg[N_NODES];
__device__ int   g_rowptr[N_NODES + 1];
__device__ int   g_bsum[SCAN_NBLK];
__device__ int   g_boff[SCAN_NBLK];
__device__ __align__(16) unsigned short g_rank[E_TRAIN];
__device__ __align__(16) unsigned short g_esrc[E_TRAIN];
__device__ float g_dinv[N_NODES];

// ---- degree + rank (4 edges/thread: TLP over ILP) ---------------------------
__global__ void k_zero() {
    int i = blockIdx.x * blockDim.x + threadIdx.x;
    if (i < N_NODES) g_deg[i] = 0;
}

__global__ void k_count(const int* __restrict__ dst) {
    int t = blockIdx.x * 256 + threadIdx.x;
    if (t < E_TRAIN / 4) {
        int4 d = __ldg((const int4*)dst + t);
        unsigned r0 = atomicAdd(&g_deg[d.x], 1);
        unsigned r1 = atomicAdd(&g_deg[d.y], 1);
        unsigned r2 = atomicAdd(&g_deg[d.z], 1);
        unsigned r3 = atomicAdd(&g_deg[d.w], 1);
        uint2 pk;
        pk.x = r0 | (r1 << 16);
        pk.y = r2 | (r3 << 16);
        ((uint2*)g_rank)[t] = pk;
    }
}

// ---- 3-phase multi-block exclusive scan -> rowptr/dinv ----------------------
__global__ __launch_bounds__(SCAN_B) void k_scan_local() {
    __shared__ int sh[SCAN_B];
    int t = threadIdx.x;
    int gid = blockIdx.x * SCAN_B + t;
    int d = (gid < N_NODES) ? g_deg[gid] : 0;
    int val = d;
    sh[t] = val;
    __syncthreads();
    for (int off = 1; off < SCAN_B; off <<= 1) {
        int v = (t >= off) ? sh[t - off] : 0;
        __syncthreads();
        val += v;
        sh[t] = val;
        __syncthreads();
    }
    if (gid < N_NODES) {
        g_rowptr[gid] = val - d;
        g_dinv[gid]   = rsqrtf((float)(d + 1));  // +1 self loop
    }
    if (t == SCAN_B - 1) g_bsum[blockIdx.x] = val;
}

__global__ void k_scan_bsum() {
    __shared__ int sh[SCAN_NBLK];
    int t = threadIdx.x;   // 64 threads
    if (t < SCAN_NBLK) sh[t] = g_bsum[t];
    __syncthreads();
    if (t == 0) {
        int run = 0;
#pragma unroll
        for (int i = 0; i < SCAN_NBLK; i++) {
            int d = sh[i];
            sh[i] = run;
            run += d;
        }
        g_rowptr[N_NODES] = run;
    }
    __syncthreads();
    if (t < SCAN_NBLK) g_boff[t] = sh[t];
}

__global__ __launch_bounds__(SCAN_B) void k_scan_add() {
    int gid = blockIdx.x * SCAN_B + threadIdx.x;
    if (gid < N_NODES) g_rowptr[gid] += __ldg(g_boff + blockIdx.x);
}

// ---- atomic-free placement (4 edges/thread) ---------------------------------
__global__ void k_place(const int* __restrict__ src, const int* __restrict__ dst) {
    int t = blockIdx.x * 256 + threadIdx.x;
    if (t < E_TRAIN / 4) {
        int4 s0 = __ldg((const int4*)src + t);
        int4 d0 = __ldg((const int4*)dst + t);
        uint2 pk = __ldg((const uint2*)g_rank + t);
        int p0 = __ldg(g_rowptr + d0.x) + (pk.x & 0xffff);
        int p1 = __ldg(g_rowptr + d0.y) + (pk.x >> 16);
        int p2 = __ldg(g_rowptr + d0.z) + (pk.y & 0xffff);
        int p3 = __ldg(g_rowptr + d0.w) + (pk.y >> 16);
        g_esrc[p0] = (unsigned short)s0.x;
        g_esrc[p1] = (unsigned short)s0.y;
        g_esrc[p2] = (unsigned short)s0.z;
        g_esrc[p3] = (unsigned short)s0.w;
    }
}

// ---- scale bufA rows by dinv (layer 1) --------------------------------------
__global__ __launch_bounds__(256) void k_scale() {
    int t = blockIdx.x * 256 + threadIdx.x;   // 3125 blocks exact
    int node = t >> 4, q = t & 15;
    float di = __ldg(g_dinv + node);
    uint2 u = *(uint2*)&g_bufA[node * PAD + q * 4];
    __half2* hp = (__half2*)&u;
    float2 f0 = __half22float2(hp[0]);
    float2 f1 = __half22float2(hp[1]);
    __half2 o0 = __floats2half2_rn(f0.x * di, f0.y * di);
    __half2 o1 = __floats2half2_rn(f1.x * di, f1.y * di);
    uint2 st; st.x = *(unsigned*)&o0; st.y = *(unsigned*)&o1;
    *(uint2*)&g_bufA[node * PAD + q * 4] = st;
}

// ---- GEMM 1: bufA = fp16(x @ W1) UNSCALED, 32 nodes/block -------------------
__global__ __launch_bounds__(256) void k_gemm1(const float* __restrict__ x,
                                               const float* __restrict__ W1) {
    __shared__ float ws[F_IN][64];
    __shared__ float xs[32][F_IN + 2];
    int tid = threadIdx.x;
    int nodeBase = blockIdx.x * 32;
    for (int t = tid; t < F_IN * 64; t += 256) {
        int k = t >> 6, j = t & 63;
        ws[k][j] = (j < HID) ? W1[k * HID + j] : 0.f;
    }
    for (int t = tid; t < 32 * F_IN; t += 256) {
        int n = t / F_IN, k = t % F_IN;
        int node = nodeBase + n;
        xs[n][k] = (node < N_NODES) ? x[node * F_IN + k] : 0.f;
    }
    __syncthreads();
    int n = tid >> 4, jq = tid & 15;
    int node0 = nodeBase + n;
    int node1 = nodeBase + n + 16;
    float4 accA = make_float4(0.f, 0.f, 0.f, 0.f);
    float4 accB = make_float4(0.f, 0.f, 0.f, 0.f);
#pragma unroll
    for (int k = 0; k < F_IN; k++) {
        float4 w = *(const float4*)&ws[k][jq * 4];
        float xv0 = xs[n][k];
        float xv1 = xs[n + 16][k];
        accA.x = fmaf(xv0, w.x, accA.x);
        accA.y = fmaf(xv0, w.y, accA.y);
        accA.z = fmaf(xv0, w.z, accA.z);
        accA.w = fmaf(xv0, w.w, accA.w);
        accB.x = fmaf(xv1, w.x, accB.x);
        accB.y = fmaf(xv1, w.y, accB.y);
        accB.z = fmaf(xv1, w.z, accB.z);
        accB.w = fmaf(xv1, w.w, accB.w);
    }
    if (node0 < N_NODES) {
        __half2 p0 = __floats2half2_rn(accA.x, accA.y);
        __half2 p1 = __floats2half2_rn(accA.z, accA.w);
        uint2 st; st.x = *(unsigned*)&p0; st.y = *(unsigned*)&p1;
        *(uint2*)&g_bufA[node0 * PAD + jq * 4] = st;
    }
    if (node1 < N_NODES) {
        __half2 p0 = __floats2half2_rn(accB.x, accB.y);
        __half2 p1 = __floats2half2_rn(accB.z, accB.w);
        uint2 st; st.x = *(unsigned*)&p0; st.y = *(unsigned*)&p1;
        *(uint2*)&g_bufA[node1 * PAD + jq * 4] = st;
    }
}

// ---- GEMM 2: bufA = fp16(dinv*(bufC @ W2)), 64 nodes/block, 4 nodes/thread --
__global__ __launch_bounds__(256) void k_gemm2(const float* __restrict__ W2) {
    __shared__ float ws[HID][64];
    __shared__ float xs[64][HID + 2];
    int tid = threadIdx.x;
    int nodeBase = blockIdx.x * 64;                 // 782 blocks (last partial)
    for (int t = tid; t < HID * 64; t += 256)
        ws[t >> 6][t & 63] = W2[t];
    for (int t = tid; t < 64 * HID; t += 256) {
        int n = t / HID, k = t % HID;
        int node = nodeBase + n;
        xs[n][k] = (node < N_NODES) ? __half2float(g_bufC[node * PAD + k]) : 0.f;
    }
    __syncthreads();
    int n = tid >> 4, jq = tid & 15;
    float4 acc0 = make_float4(0.f, 0.f, 0.f, 0.f);
    float4 acc1 = make_float4(0.f, 0.f, 0.f, 0.f);
    float4 acc2 = make_float4(0.f, 0.f, 0.f, 0.f);
    float4 acc3 = make_float4(0.f, 0.f, 0.f, 0.f);
#pragma unroll
    for (int k = 0; k < HID; k++) {
        float4 w = *(const float4*)&ws[k][jq * 4];
        float xv0 = xs[n][k];
        float xv1 = xs[n + 16][k];
        float xv2 = xs[n + 32][k];
        float xv3 = xs[n + 48][k];
        acc0.x = fmaf(xv0, w.x, acc0.x); acc0.y = fmaf(xv0, w.y, acc0.y);
        acc0.z = fmaf(xv0, w.z, acc0.z); acc0.w = fmaf(xv0, w.w, acc0.w);
        acc1.x = fmaf(xv1, w.x, acc1.x); acc1.y = fmaf(xv1, w.y, acc1.y);
        acc1.z = fmaf(xv1, w.z, acc1.z); acc1.w = fmaf(xv1, w.w, acc1.w);
        acc2.x = fmaf(xv2, w.x, acc2.x); acc2.y = fmaf(xv2, w.y, acc2.y);
        acc2.z = fmaf(xv2, w.z, acc2.z); acc2.w = fmaf(xv2, w.w, acc2.w);
        acc3.x = fmaf(xv3, w.x, acc3.x); acc3.y = fmaf(xv3, w.y, acc3.y);
        acc3.z = fmaf(xv3, w.z, acc3.z); acc3.w = fmaf(xv3, w.w, acc3.w);
    }
#pragma unroll
    for (int p = 0; p < 4; p++) {
        int node = nodeBase + n + p * 16;
        if (node < N_NODES) {
            float4 a = (p == 0) ? acc0 : (p == 1) ? acc1 : (p == 2) ? acc2 : acc3;
            float di = __ldg(g_dinv + node);
            __half2 p0 = __floats2half2_rn(a.x * di, a.y * di);
            __half2 p1 = __floats2half2_rn(a.z * di, a.w * di);
            uint2 st; st.x = *(unsigned*)&p0; st.y = *(unsigned*)&p1;
            *(uint2*)&g_bufA[node * PAD + jq * 4] = st;
        }
    }
}

// ---- CSR aggregation + fused epilogue (R14 gather body, fp16 out) -----------
#define ACCUM(U) do {                                                   \
        __half2* hp = (__half2*)&(U);                                   \
        float2 f0 = __half22float2(hp[0]);                              \
        float2 f1 = __half22float2(hp[1]);                              \
        float2 f2 = __half22float2(hp[2]);                              \
        float2 f3 = __half22float2(hp[3]);                              \
        a0 += f0.x; a1 += f0.y; a2 += f1.x; a3 += f1.y;                 \
        a4 += f2.x; a5 += f2.y; a6 += f3.x; a7 += f3.y;                 \
    } while (0)

#define RED(off) do {                                                   \
        a0 += __shfl_xor_sync(0xffffffffu, a0, off);                    \
        a1 += __shfl_xor_sync(0xffffffffu, a1, off);                    \
        a2 += __shfl_xor_sync(0xffffffffu, a2, off);                    \
        a3 += __shfl_xor_sync(0xffffffffu, a3, off);                    \
        a4 += __shfl_xor_sync(0xffffffffu, a4, off);                    \
        a5 += __shfl_xor_sync(0xffffffffu, a5, off);                    \
        a6 += __shfl_xor_sync(0xffffffffu, a6, off);                    \
        a7 += __shfl_xor_sync(0xffffffffu, a7, off);                    \
    } while (0)

// OUT: 0 -> g_bufC (layer 1), 1 -> g_z (layer 2). Both read g_bufA.
template <int CH, int NB, bool RELU, int OUT>
__global__ __launch_bounds__(256) void k_agg(const float* __restrict__ bias) {
    int node = (blockIdx.x * 256 + threadIdx.x) >> 5;   // 6250 blocks exact
    int lane = threadIdx.x & 31;
    int g = lane >> 3, q = lane & 7;
    int rp = g_rowptr[node], re = g_rowptr[node + 1];
    float a0 = 0.f, a1 = 0.f, a2 = 0.f, a3 = 0.f;
    float a4 = 0.f, a5 = 0.f, a6 = 0.f, a7 = 0.f;
    const uint4* rows = (const uint4*)g_bufA;
    const bool act = (CH == 8) || (q < CH);

    if (g == 0 && act) {                                // self loop
        uint4 u = __ldg(rows + node * 8 + q);
        ACCUM(u);
    }
    int e = rp + g;
    for (; e + 12 < re; e += 16) {
        int s0 = (int)__ldg(g_esrc + e);
        int s1 = (int)__ldg(g_esrc + e + 4);
        int s2 = (int)__ldg(g_esrc + e + 8);
        int s3 = (int)__ldg(g_esrc + e + 12);
        if (act) {
            uint4 u0 = __ldg(rows + s0 * 8 + q);
            uint4 u1 = __ldg(rows + s1 * 8 + q);
            uint4 u2 = __ldg(rows + s2 * 8 + q);
            uint4 u3 = __ldg(rows + s3 * 8 + q);
            ACCUM(u0); ACCUM(u1); ACCUM(u2); ACCUM(u3);
        }
    }
    for (; e + 4 < re; e += 8) {
        int s0 = (int)__ldg(g_esrc + e);
        int s1 = (int)__ldg(g_esrc + e + 4);
        if (act) {
            uint4 u0 = __ldg(rows + s0 * 8 + q);
            uint4 u1 = __ldg(rows + s1 * 8 + q);
            ACCUM(u0); ACCUM(u1);
        }
    }
    if (e < re) {
        int s0 = (int)__ldg(g_esrc + e);
        if (act) {
            uint4 u0 = __ldg(rows + s0 * 8 + q);
            ACCUM(u0);
        }
    }
    RED(8);
    RED(16);

    if (g == 0 && act) {
        float di = g_dinv[node];
        int j0 = q * 8;
        float acc[8] = {a0, a1, a2, a3, a4, a5, a6, a7};
        float v[8];
#pragma unroll
        for (int i = 0; i < 8; i++) {
            int j = j0 + i;
            float bv = (j < NB) ? __ldg(bias + j) : 0.f;
            float r = fmaf(di, acc[i], bv);
            if (RELU) r = fmaxf(r, 0.f);
            v[i] = r;
        }
        __half2 h0 = __floats2half2_rn(v[0], v[1]);
        __half2 h1 = __floats2half2_rn(v[2], v[3]);
        __half2 h2 = __floats2half2_rn(v[4], v[5]);
        __half2 h3 = __floats2half2_rn(v[6], v[7]);
        uint4 st;
        st.x = *(unsigned*)&h0; st.y = *(unsigned*)&h1;
        st.z = *(unsigned*)&h2; st.w = *(unsigned*)&h3;
        __half* outp = (OUT == 0) ? g_bufC : g_z;
        *(uint4*)&outp[node * PAD + j0] = st;
    }
}

#undef ACCUM
#undef RED

// ---- decode: logits[e] = dot64(z[a], z[b]), z fp16 --------------------------
__global__ void k_decode(const int* __restrict__ pos,
                         const int* __restrict__ neg,
                         float* __restrict__ out) {
    int gt = blockIdx.x * 256 + threadIdx.x;   // 12500 blocks exact
    int e = gt >> 3;
    int j = gt & 7;
    int a, b;
    if (e < EP) { a = pos[e];        b = pos[EP + e]; }
    else        { int e2 = e - EP;  a = neg[e2];     b = neg[EN + e2]; }
    uint4 ua = __ldg((const uint4*)(g_z + a * PAD) + j);
    uint4 ub = __ldg((const uint4*)(g_z + b * PAD) + j);
    __half2* ha = (__half2*)&ua;
    __half2* hb = (__half2*)&ub;
    float s = 0.f;
#pragma unroll
    for (int i = 0; i < 4; i++) {
        float2 fa = __half22float2(ha[i]);
        float2 fb = __half22float2(hb[i]);
        s = fmaf(fa.x, fb.x, s);
        s = fmaf(fa.y, fb.y, s);
    }
#pragma unroll
    for (int o = 4; o; o >>= 1) s += __shfl_xor_sync(0xffffffffu, s, o);
    if (j == 0) out[e] = s;
}

// ---------------------------------------------------------------------------
extern "C" void kernel_launch(void* const* d_in, const int* in_sizes, int n_in,
                              void* d_out, int out_size) {
    const float* x   = (const float*)d_in[0];
    const int*   tr  = (const int*)d_in[1];
    const int*   pos = (const int*)d_in[2];
    const int*   neg = (const int*)d_in[3];
    const float* W1  = (const float*)d_in[4];
    const float* b1  = (const float*)d_in[5];
    const float* W2  = (const float*)d_in[6];
    const float* b2  = (const float*)d_in[7];
    float* out = (float*)d_out;

    const int* src = tr;
    const int* dst = tr + E_TRAIN;

    static cudaStream_t sB = nullptr;
    static cudaEvent_t  evStart = nullptr, evScan = nullptr, evG1 = nullptr;
    if (sB == nullptr) {
        cudaStreamCreateWithFlags(&sB, cudaStreamNonBlocking);
        cudaEventCreateWithFlags(&evStart, cudaEventDisableTiming);
        cudaEventCreateWithFlags(&evScan,  cudaEventDisableTiming);
        cudaEventCreateWithFlags(&evG1,    cudaEventDisableTiming);
    }

    // Fork at t=0: gemm1 (unscaled -> no build dependency) on stream B.
    cudaEventRecord(evStart, 0);
    cudaStreamWaitEvent(sB, evStart, 0);
    k_gemm1<<<(N_NODES + 31) / 32, 256, 0, sB>>>(x, W1);

    // CSR build on default stream, concurrent with gemm1.
    k_zero<<<(N_NODES + 255) / 256, 256>>>();
    k_count<<<(E_TRAIN / 4 + 255) / 256, 256>>>(dst);
    k_scan_local<<<SCAN_NBLK, SCAN_B>>>();
    k_scan_bsum<<<1, 64>>>();
    k_scan_add<<<SCAN_NBLK, SCAN_B>>>();
    cudaEventRecord(evScan, 0);          // dinv ready

    // Stream B: scale bufA by dinv (after gemm1 + scan), concurrent w/ place.
    cudaStreamWaitEvent(sB, evScan, 0);
    k_scale<<<N_NODES * 16 / 256, 256, 0, sB>>>();
    cudaEventRecord(evG1, sB);

    k_place<<<(E_TRAIN / 4 + 255) / 256, 256>>>(src, dst);

    // Join, then layer 1 aggregation (fp16 h1 out).
    cudaStreamWaitEvent(0, evG1, 0);
    k_agg<7, HID, true, 0><<<N_NODES * 32 / 256, 256>>>(b1);

    // layer 2
    k_gemm2<<<(N_NODES + 63) / 64, 256>>>(W2);
    k_agg<8, DOUT, false, 1><<<N_NODES * 32 / 256, 256>>>(b2);

    // decode
    k_decode<<<(EP + EN) * 8 / 256, 256>>>(pos, neg, out);
}